// round 8
// baseline (speedup 1.0000x reference)
#include <cuda_runtime.h>

#define RB 131072
#define RT 6
#define RV 31
#define NJP 16           // j-pairs; j=31 is zero-padded
#define HST 33           // h smem row stride (words): bank (33*l+k)%32=(l+k)%32

// Inter-layer activation scratch: [B][T][V], ~93 MiB.
__device__ float g_scratch[(size_t)RB * RT * RV];

// tanh(x) = 1 - 2/(exp(2x)+1); MUFU-based, rel err ~1e-6, saturates at +/-1.
__device__ __forceinline__ float tanh_fast(float x) {
    float e = __expf(2.0f * x);
    return 1.0f - __fdividef(2.0f, e + 1.0f);
}

// w4[k*NJP + jp] = {Wih[j0,k], Whh[j0,k], Wih[j1,k], Whh[j1,k]}, j1==31 -> 0
__device__ __forceinline__ void fill_w4(float4* w4, float* bsum,
                                        const float* __restrict__ Wih,
                                        const float* __restrict__ Whh,
                                        const float* __restrict__ bih,
                                        const float* __restrict__ bhh,
                                        int tid)
{
    for (int i = tid; i < RV * NJP; i += 128) {
        int k = i / NJP, jp = i - k * NJP;
        int j0 = 2 * jp, j1 = j0 + 1;
        float4 v;
        v.x = Wih[j0 * RV + k];
        v.y = Whh[j0 * RV + k];
        v.z = (j1 < RV) ? Wih[j1 * RV + k] : 0.0f;
        v.w = (j1 < RV) ? Whh[j1 * RV + k] : 0.0f;
        w4[i] = v;
    }
    if (tid < 32) bsum[tid] = (tid < RV) ? (bih[tid] + bhh[tid]) : 0.0f;
}

// One RNN layer over all T steps; one batch element per thread.
// Recurrent state h lives in a private smem row -> regs = acc[32] + temps only.
__global__ void __launch_bounds__(128, 4)
rnn_layer(const float* xin_ext, int use_ext_in,
          const float* __restrict__ h0,
          const float* __restrict__ Wih, const float* __restrict__ Whh,
          const float* __restrict__ bih, const float* __restrict__ bhh)
{
    __shared__ float4 w4[RV * NJP];
    __shared__ float bsum[32];
    __shared__ float hs[128 * HST];

    const int tid = threadIdx.x;
    fill_w4(w4, bsum, Wih, Whh, bih, bhh, tid);

    const size_t b = (size_t)blockIdx.x * 128 + tid;
    float* hrow = hs + tid * HST;          // private row, no syncs needed
#pragma unroll
    for (int j = 0; j < RV; ++j) hrow[j] = h0[b * RV + j];
    __syncthreads();                       // for w4/bsum

    const float* xr = (use_ext_in ? xin_ext : g_scratch) + b * (RT * RV);
    float* orow = g_scratch + b * (RT * RV);

#pragma unroll 1
    for (int t = 0; t < RT; ++t) {
        float acc[2 * NJP];
#pragma unroll
        for (int j = 0; j < 2 * NJP; ++j) acc[j] = bsum[j];

#pragma unroll
        for (int k = 0; k < RV; ++k) {
            const float xk = xr[k];        // L1-resident row
            const float hk = hrow[k];      // conflict-free LDS
            const float4* wr = w4 + k * NJP;
#pragma unroll
            for (int jp = 0; jp < NJP; ++jp) {
                float4 w = wr[jp];         // broadcast LDS.128
                acc[2 * jp]     = fmaf(w.x, xk, fmaf(w.y, hk, acc[2 * jp]));
                acc[2 * jp + 1] = fmaf(w.z, xk, fmaf(w.w, hk, acc[2 * jp + 1]));
            }
        }
#pragma unroll
        for (int j = 0; j < RV; ++j) {
            float v = tanh_fast(acc[j]);
            hrow[j] = v;
            orow[j] = v;
        }
        xr += RV;
        orow += RV;
    }
}

// Layer 2 recurrence (no intermediate stores) + linear + tanh + softmax.
__global__ void __launch_bounds__(128, 4)
rnn_final(const float* __restrict__ h0,
          const float* __restrict__ Wih, const float* __restrict__ Whh,
          const float* __restrict__ bih, const float* __restrict__ bhh,
          const float* __restrict__ Wlin, const float* __restrict__ blin,
          float* __restrict__ out)
{
    __shared__ float4 w4[RV * NJP];
    __shared__ float bsum[32];
    __shared__ float2 wl2[RV * NJP];   // {Wlin[j0,k], Wlin[j1,k]}
    __shared__ float bl[32];
    __shared__ float hs[128 * HST];

    const int tid = threadIdx.x;
    fill_w4(w4, bsum, Wih, Whh, bih, bhh, tid);
    for (int i = tid; i < RV * NJP; i += 128) {
        int k = i / NJP, jp = i - k * NJP;
        int j0 = 2 * jp, j1 = j0 + 1;
        wl2[i] = make_float2(Wlin[j0 * RV + k],
                             (j1 < RV) ? Wlin[j1 * RV + k] : 0.0f);
    }
    if (tid < 32) bl[tid] = (tid < RV) ? blin[tid] : 0.0f;

    const size_t b = (size_t)blockIdx.x * 128 + tid;
    float* hrow = hs + tid * HST;
#pragma unroll
    for (int j = 0; j < RV; ++j) hrow[j] = h0[b * RV + j];
    __syncthreads();

    const float* xr = g_scratch + b * (RT * RV);

#pragma unroll 1
    for (int t = 0; t < RT; ++t) {
        float acc[2 * NJP];
#pragma unroll
        for (int j = 0; j < 2 * NJP; ++j) acc[j] = bsum[j];

#pragma unroll
        for (int k = 0; k < RV; ++k) {
            const float xk = xr[k];
            const float hk = hrow[k];
            const float4* wr = w4 + k * NJP;
#pragma unroll
            for (int jp = 0; jp < NJP; ++jp) {
                float4 w = wr[jp];
                acc[2 * jp]     = fmaf(w.x, xk, fmaf(w.y, hk, acc[2 * jp]));
                acc[2 * jp + 1] = fmaf(w.z, xk, fmaf(w.w, hk, acc[2 * jp + 1]));
            }
        }
#pragma unroll
        for (int j = 0; j < RV; ++j) hrow[j] = tanh_fast(acc[j]);
        xr += RV;
    }

    // linear: y[j] = blin[j] + sum_k Wlin[j,k] * h[k]
    float y[2 * NJP];
#pragma unroll
    for (int j = 0; j < 2 * NJP; ++j) y[j] = bl[j];
#pragma unroll
    for (int k = 0; k < RV; ++k) {
        const float hk = hrow[k];
        const float2* wr = wl2 + k * NJP;
#pragma unroll
        for (int jp = 0; jp < NJP; ++jp) {
            float2 w = wr[jp];             // broadcast LDS.64
            y[2 * jp]     = fmaf(w.x, hk, y[2 * jp]);
            y[2 * jp + 1] = fmaf(w.y, hk, y[2 * jp + 1]);
        }
    }
#pragma unroll
    for (int j = 0; j < RV; ++j) y[j] = tanh_fast(y[j]);

    // softmax over V
    float m = y[0];
#pragma unroll
    for (int j = 1; j < RV; ++j) m = fmaxf(m, y[j]);
    float s = 0.0f;
#pragma unroll
    for (int j = 0; j < RV; ++j) { y[j] = __expf(y[j] - m); s += y[j]; }
    const float inv = __fdividef(1.0f, s);
#pragma unroll
    for (int j = 0; j < RV; ++j) out[b * RV + j] = y[j] * inv;
}

extern "C" void kernel_launch(void* const* d_in, const int* in_sizes, int n_in,
                              void* d_out, int out_size)
{
    const float* inp  = (const float*)d_in[0];  // [B,T,V]
    const float* h0   = (const float*)d_in[1];  // [L,B,V]
    const float* Wih  = (const float*)d_in[2];  // [L,V,V]
    const float* Whh  = (const float*)d_in[3];  // [L,V,V]
    const float* bih  = (const float*)d_in[4];  // [L,V]
    const float* bhh  = (const float*)d_in[5];  // [L,V]
    const float* Wlin = (const float*)d_in[6];  // [V,V]
    const float* blin = (const float*)d_in[7];  // [V]
    float* out = (float*)d_out;                 // [B,V]

    (void)in_sizes; (void)n_in; (void)out_size;

    const dim3 grid(RB / 128), block(128);

    // layer 0: inp -> scratch
    rnn_layer<<<grid, block>>>(inp, 1, h0, Wih, Whh, bih, bhh);
    // layer 1: scratch -> scratch (in-place, each thread owns its row)
    rnn_layer<<<grid, block>>>(nullptr, 0, h0 + (size_t)RB * RV,
                               Wih + RV * RV, Whh + RV * RV,
                               bih + RV, bhh + RV);
    // layer 2 + linear + tanh + softmax
    rnn_final<<<grid, block>>>(h0 + 2 * (size_t)RB * RV,
                               Wih + 2 * RV * RV, Whh + 2 * RV * RV,
                               bih + 2 * RV, bhh + 2 * RV,
                               Wlin, blin, out);
}

// round 9
// speedup vs baseline: 6.7843x; 6.7843x over previous
#include <cuda_runtime.h>

#define RB 131072
#define RT 6
#define RV 31
#define NJP 16           // j-pairs; j=31 zero-padded
#define XS  (RT * RV)    // 186, row stride in [B,T,V]

// Inter-layer activation scratch: [B][T][V], ~93 MiB.
__device__ float g_scratch[(size_t)RB * RT * RV];

// tanh(x) = 1 - 2/(exp(2x)+1); MUFU-based, rel err ~1e-6, saturates at +/-1.
__device__ __forceinline__ float tanh_fast(float x) {
    float e = __expf(2.0f * x);
    return 1.0f - __fdividef(2.0f, e + 1.0f);
}

// w4[k*NJP + jp] = {Wih[j0,k], Whh[j0,k], Wih[j1,k], Whh[j1,k]}, j1==31 -> 0
__device__ __forceinline__ void fill_w4(float4* w4, float* bsum,
                                        const float* __restrict__ Wih,
                                        const float* __restrict__ Whh,
                                        const float* __restrict__ bih,
                                        const float* __restrict__ bhh,
                                        int tid)
{
    for (int i = tid; i < RV * NJP; i += 128) {
        int k = i / NJP, jp = i - k * NJP;
        int j0 = 2 * jp, j1 = j0 + 1;
        float4 v;
        v.x = Wih[j0 * RV + k];
        v.y = Whh[j0 * RV + k];
        v.z = (j1 < RV) ? Wih[j1 * RV + k] : 0.0f;
        v.w = (j1 < RV) ? Whh[j1 * RV + k] : 0.0f;
        w4[i] = v;
    }
    if (tid < 32) bsum[tid] = (tid < RV) ? (bih[tid] + bhh[tid]) : 0.0f;
}

// One RNN layer over all T steps; one batch element per thread.
// All global x/o traffic staged through smem with coalesced cooperative
// loads/stores. Compute reads xs[tid*31+k]: stride-31 -> conflict-free.
__global__ void __launch_bounds__(128, 4)
rnn_layer(const float* xin_ext, int use_ext_in,
          const float* __restrict__ h0,
          const float* __restrict__ Wih, const float* __restrict__ Whh,
          const float* __restrict__ bih, const float* __restrict__ bhh)
{
    __shared__ float4 w4[RV * NJP];   // 7936 B
    __shared__ float bsum[32];
    __shared__ float xs[128 * RV];    // 15872 B staging (h0 / x[t] / o[t])

    const int tid = threadIdx.x;
    fill_w4(w4, bsum, Wih, Whh, bih, bhh, tid);

    const size_t blk0 = (size_t)blockIdx.x * 128;     // first batch elem of CTA

    // h0 block is 128*31 contiguous floats -> perfectly coalesced via staging
    {
        const float* h0b = h0 + blk0 * RV;
        for (int i = tid; i < 128 * RV; i += 128) xs[i] = h0b[i];
    }
    __syncthreads();

    float h[RV];
#pragma unroll
    for (int j = 0; j < RV; ++j) h[j] = xs[tid * RV + j];

    const float* xbase = (use_ext_in ? xin_ext : g_scratch) + blk0 * XS;
    float* obase = g_scratch + blk0 * XS;

#pragma unroll 1
    for (int t = 0; t < RT; ++t) {
        __syncthreads();                    // xs reads of prev phase done
        // coop load x[t]: row r at xbase + r*186 + t*31, 31 contiguous floats
        {
            const float* src = xbase + t * RV;
            for (int i = tid; i < 128 * RV; i += 128) {
                int r = i / RV, c = i - r * RV;
                xs[i] = src[r * XS + c];
            }
        }
        __syncthreads();

        float acc[2 * NJP];
#pragma unroll
        for (int j = 0; j < 2 * NJP; ++j) acc[j] = bsum[j];

#pragma unroll
        for (int k = 0; k < RV; ++k) {
            const float xk = xs[tid * RV + k];   // conflict-free LDS
            const float hk = h[k];
            const float4* wr = w4 + k * NJP;
#pragma unroll
            for (int jp = 0; jp < NJP; ++jp) {
                float4 w = wr[jp];               // broadcast LDS.128
                acc[2 * jp]     = fmaf(w.x, xk, fmaf(w.y, hk, acc[2 * jp]));
                acc[2 * jp + 1] = fmaf(w.z, xk, fmaf(w.w, hk, acc[2 * jp + 1]));
            }
        }
        __syncthreads();                    // all xs reads done before reuse
#pragma unroll
        for (int j = 0; j < RV; ++j) {
            float v = tanh_fast(acc[j]);
            h[j] = v;
            xs[tid * RV + j] = v;
        }
        __syncthreads();
        // coop store o[t] (coalesced)
        {
            float* dst = obase + t * RV;
            for (int i = tid; i < 128 * RV; i += 128) {
                int r = i / RV, c = i - r * RV;
                dst[r * XS + c] = xs[i];
            }
        }
    }
}

// Layer 2 recurrence (no intermediate activation stores) + linear + tanh + softmax.
__global__ void __launch_bounds__(128, 4)
rnn_final(const float* __restrict__ h0,
          const float* __restrict__ Wih, const float* __restrict__ Whh,
          const float* __restrict__ bih, const float* __restrict__ bhh,
          const float* __restrict__ Wlin, const float* __restrict__ blin,
          float* __restrict__ out)
{
    __shared__ float4 w4[RV * NJP];
    __shared__ float bsum[32];
    __shared__ float2 wl2[RV * NJP];  // {Wlin[j0,k], Wlin[j1,k]}
    __shared__ float bl[32];
    __shared__ float xs[128 * RV];

    const int tid = threadIdx.x;
    fill_w4(w4, bsum, Wih, Whh, bih, bhh, tid);
    for (int i = tid; i < RV * NJP; i += 128) {
        int k = i / NJP, jp = i - k * NJP;
        int j0 = 2 * jp, j1 = j0 + 1;
        wl2[i] = make_float2(Wlin[j0 * RV + k],
                             (j1 < RV) ? Wlin[j1 * RV + k] : 0.0f);
    }
    if (tid < 32) bl[tid] = (tid < RV) ? blin[tid] : 0.0f;

    const size_t blk0 = (size_t)blockIdx.x * 128;
    {
        const float* h0b = h0 + blk0 * RV;
        for (int i = tid; i < 128 * RV; i += 128) xs[i] = h0b[i];
    }
    __syncthreads();

    float h[RV];
#pragma unroll
    for (int j = 0; j < RV; ++j) h[j] = xs[tid * RV + j];

    const float* xbase = g_scratch + blk0 * XS;

#pragma unroll 1
    for (int t = 0; t < RT; ++t) {
        __syncthreads();
        {
            const float* src = xbase + t * RV;
            for (int i = tid; i < 128 * RV; i += 128) {
                int r = i / RV, c = i - r * RV;
                xs[i] = src[r * XS + c];
            }
        }
        __syncthreads();

        float acc[2 * NJP];
#pragma unroll
        for (int j = 0; j < 2 * NJP; ++j) acc[j] = bsum[j];

#pragma unroll
        for (int k = 0; k < RV; ++k) {
            const float xk = xs[tid * RV + k];
            const float hk = h[k];
            const float4* wr = w4 + k * NJP;
#pragma unroll
            for (int jp = 0; jp < NJP; ++jp) {
                float4 w = wr[jp];
                acc[2 * jp]     = fmaf(w.x, xk, fmaf(w.y, hk, acc[2 * jp]));
                acc[2 * jp + 1] = fmaf(w.z, xk, fmaf(w.w, hk, acc[2 * jp + 1]));
            }
        }
#pragma unroll
        for (int j = 0; j < RV; ++j) h[j] = tanh_fast(acc[j]);
    }

    // linear + tanh
    float y[2 * NJP];
#pragma unroll
    for (int j = 0; j < 2 * NJP; ++j) y[j] = bl[j];
#pragma unroll
    for (int k = 0; k < RV; ++k) {
        const float hk = h[k];
        const float2* wr = wl2 + k * NJP;
#pragma unroll
        for (int jp = 0; jp < NJP; ++jp) {
            float2 w = wr[jp];
            y[2 * jp]     = fmaf(w.x, hk, y[2 * jp]);
            y[2 * jp + 1] = fmaf(w.y, hk, y[2 * jp + 1]);
        }
    }
#pragma unroll
    for (int j = 0; j < RV; ++j) y[j] = tanh_fast(y[j]);

    // softmax over V
    float m = y[0];
#pragma unroll
    for (int j = 1; j < RV; ++j) m = fmaxf(m, y[j]);
    float s = 0.0f;
#pragma unroll
    for (int j = 0; j < RV; ++j) { y[j] = __expf(y[j] - m); s += y[j]; }
    const float inv = __fdividef(1.0f, s);

    // stage result, coop store (out block is 128*31 contiguous floats)
    __syncthreads();
#pragma unroll
    for (int j = 0; j < RV; ++j) xs[tid * RV + j] = y[j] * inv;
    __syncthreads();
    {
        float* ob = out + blk0 * RV;
        for (int i = tid; i < 128 * RV; i += 128) ob[i] = xs[i];
    }
}

extern "C" void kernel_launch(void* const* d_in, const int* in_sizes, int n_in,
                              void* d_out, int out_size)
{
    const float* inp  = (const float*)d_in[0];  // [B,T,V]
    const float* h0   = (const float*)d_in[1];  // [L,B,V]
    const float* Wih  = (const float*)d_in[2];  // [L,V,V]
    const float* Whh  = (const float*)d_in[3];  // [L,V,V]
    const float* bih  = (const float*)d_in[4];  // [L,V]
    const float* bhh  = (const float*)d_in[5];  // [L,V]
    const float* Wlin = (const float*)d_in[6];  // [V,V]
    const float* blin = (const float*)d_in[7];  // [V]
    float* out = (float*)d_out;                 // [B,V]

    (void)in_sizes; (void)n_in; (void)out_size;

    const dim3 grid(RB / 128), block(128);

    // layer 0: inp -> scratch
    rnn_layer<<<grid, block>>>(inp, 1, h0, Wih, Whh, bih, bhh);
    // layer 1: scratch -> scratch (in-place, per-CTA rows, read-before-write per t)
    rnn_layer<<<grid, block>>>(nullptr, 0, h0 + (size_t)RB * RV,
                               Wih + RV * RV, Whh + RV * RV,
                               bih + RV, bhh + RV);
    // layer 2 + linear + tanh + softmax
    rnn_final<<<grid, block>>>(h0 + 2 * (size_t)RB * RV,
                               Wih + 2 * RV * RV, Whh + 2 * RV * RV,
                               bih + 2 * RV, bhh + 2 * RV,
                               Wlin, blin, out);
}

// round 10
// speedup vs baseline: 7.2882x; 1.0743x over previous
#include <cuda_runtime.h>

#define RB 131072
#define RT 6
#define RV 31
#define NJP 16           // j-pairs; j=31 zero-padded
#define XS  (RT * RV)    // 186, row stride of inp [B,T,V]
#define CTAB 128         // batch elems per CTA
#define PLANE ((size_t)RB * RV)   // one timestep plane in [T,B,V]

// Inter-layer activation scratch, TIME-MAJOR [T][B][V]: per-(t,CTA) block is
// 128*31 contiguous floats -> flat float4 staging copies.
__device__ float g_scratch[(size_t)RT * RB * RV];

typedef unsigned long long u64;

__device__ __forceinline__ u64 pkdup(float a) {
    u64 r;
    asm("mov.b64 %0, {%1, %1};" : "=l"(r) : "f"(a));
    return r;
}
__device__ __forceinline__ u64 pk2(float a, float b) {
    u64 r;
    asm("mov.b64 %0, {%1, %2};" : "=l"(r) : "f"(a), "f"(b));
    return r;
}
__device__ __forceinline__ void upk2(u64 v, float& x, float& y) {
    asm("mov.b64 {%0, %1}, %2;" : "=f"(x), "=f"(y) : "l"(v));
}
// Blackwell packed dual fp32 FMA; bit-identical to two fmaf.
__device__ __forceinline__ u64 ffma2(u64 a, u64 b, u64 c) {
    u64 d;
    asm("fma.rn.f32x2 %0, %1, %2, %3;" : "=l"(d) : "l"(a), "l"(b), "l"(c));
    return d;
}

// tanh(x) = 1 - 2/(exp(2x)+1); MUFU-based, rel err ~1e-6, saturates at +/-1.
__device__ __forceinline__ float tanh_fast(float x) {
    float e = __expf(2.0f * x);
    return 1.0f - __fdividef(2.0f, e + 1.0f);
}

// w2[k*NJP+jp] = { {Wih[j0,k],Wih[j1,k]}, {Whh[j0,k],Whh[j1,k]} }, j1==31 -> 0
__device__ __forceinline__ void fill_w(ulonglong2* w2, u64* bias2,
                                       const float* __restrict__ Wih,
                                       const float* __restrict__ Whh,
                                       const float* __restrict__ bih,
                                       const float* __restrict__ bhh,
                                       int tid)
{
    for (int i = tid; i < RV * NJP; i += CTAB) {
        int k = i / NJP, jp = i - k * NJP;
        int j0 = 2 * jp, j1 = j0 + 1;
        float a0 = Wih[j0 * RV + k];
        float a1 = (j1 < RV) ? Wih[j1 * RV + k] : 0.0f;
        float c0 = Whh[j0 * RV + k];
        float c1 = (j1 < RV) ? Whh[j1 * RV + k] : 0.0f;
        w2[i].x = pk2(a0, a1);
        w2[i].y = pk2(c0, c1);
    }
    if (tid < NJP) {
        int j0 = 2 * tid, j1 = j0 + 1;
        bias2[tid] = pk2(bih[j0] + bhh[j0],
                         (j1 < RV) ? (bih[j1] + bhh[j1]) : 0.0f);
    }
}

// Flat float4 copy of one CTA block (3968 floats = 992 float4).
__device__ __forceinline__ void copy4(float* __restrict__ dst,
                                      const float* __restrict__ src, int tid)
{
    const float4* s4 = (const float4*)src;
    float4* d4 = (float4*)dst;
    for (int i = tid; i < CTAB * RV / 4; i += CTAB) d4[i] = s4[i];
}

// One RNN layer over all T steps; one batch element per thread.
__global__ void __launch_bounds__(CTAB, 4)
rnn_layer(const float* xin_ext, int use_ext_in,
          const float* __restrict__ h0,
          const float* __restrict__ Wih, const float* __restrict__ Whh,
          const float* __restrict__ bih, const float* __restrict__ bhh)
{
    __shared__ ulonglong2 w2[RV * NJP];   // 7936 B
    __shared__ u64 bias2[NJP];
    __shared__ float xs[CTAB * RV];       // 15872 B staging

    const int tid = threadIdx.x;
    fill_w(w2, bias2, Wih, Whh, bih, bhh, tid);

    const size_t blk0 = (size_t)blockIdx.x * CTAB;

    // h0 block: contiguous -> flat copy then per-thread read
    copy4(xs, h0 + blk0 * RV, tid);
    __syncthreads();

    float h[RV];
#pragma unroll
    for (int j = 0; j < RV; ++j) h[j] = xs[tid * RV + j];

#pragma unroll 1
    for (int t = 0; t < RT; ++t) {
        __syncthreads();                        // xs reads of prev phase done
        if (use_ext_in) {
            // inp is [B,T,V]: strided rows, strength-reduced (r,c) indexing
            const float* src = xin_ext + blk0 * XS + t * RV;
            int r = tid / RV, c = tid - (tid / RV) * RV;
#pragma unroll 1
            for (int it = 0; it < RV; ++it) {   // 31*128 = 3968 elems
                xs[r * RV + c] = src[r * XS + c];
                r += 4; c += 4;                  // +128 = +4*31 +4
                if (c >= RV) { c -= RV; r += 1; }
            }
        } else {
            copy4(xs, g_scratch + t * PLANE + blk0 * RV, tid);
        }
        __syncthreads();

        u64 acc[NJP];
#pragma unroll
        for (int jp = 0; jp < NJP; ++jp) acc[jp] = bias2[jp];

#pragma unroll
        for (int k = 0; k < RV; ++k) {
            const u64 xk2 = pkdup(xs[tid * RV + k]);
            const u64 hk2 = pkdup(h[k]);
            const ulonglong2* wr = w2 + k * NJP;
#pragma unroll
            for (int jp = 0; jp < NJP; ++jp) {
                ulonglong2 w = wr[jp];            // broadcast LDS.128
                acc[jp] = ffma2(w.x, xk2, acc[jp]);
                acc[jp] = ffma2(w.y, hk2, acc[jp]);
            }
        }
        __syncthreads();                        // xs reads done before overwrite
#pragma unroll
        for (int jp = 0; jp < NJP; ++jp) {
            float a0, a1;
            upk2(acc[jp], a0, a1);
            int j0 = 2 * jp, j1 = j0 + 1;
            float v0 = tanh_fast(a0);
            h[j0] = v0;
            xs[tid * RV + j0] = v0;
            if (j1 < RV) {
                float v1 = tanh_fast(a1);
                h[j1] = v1;
                xs[tid * RV + j1] = v1;
            }
        }
        __syncthreads();
        copy4(g_scratch + t * PLANE + blk0 * RV, xs, tid);  // coalesced store
    }
}

// Layer 2 recurrence (no activation stores) + linear + tanh + softmax.
__global__ void __launch_bounds__(CTAB, 4)
rnn_final(const float* __restrict__ h0,
          const float* __restrict__ Wih, const float* __restrict__ Whh,
          const float* __restrict__ bih, const float* __restrict__ bhh,
          const float* __restrict__ Wlin, const float* __restrict__ blin,
          float* __restrict__ out)
{
    __shared__ ulonglong2 w2[RV * NJP];
    __shared__ u64 bias2[NJP];
    __shared__ u64 wl[RV * NJP];          // {Wlin[j0,k], Wlin[j1,k]}
    __shared__ u64 bl[NJP];
    __shared__ float xs[CTAB * RV];

    const int tid = threadIdx.x;
    fill_w(w2, bias2, Wih, Whh, bih, bhh, tid);
    for (int i = tid; i < RV * NJP; i += CTAB) {
        int k = i / NJP, jp = i - k * NJP;
        int j0 = 2 * jp, j1 = j0 + 1;
        wl[i] = pk2(Wlin[j0 * RV + k], (j1 < RV) ? Wlin[j1 * RV + k] : 0.0f);
    }
    if (tid < NJP) {
        int j0 = 2 * tid, j1 = j0 + 1;
        bl[tid] = pk2(blin[j0], (j1 < RV) ? blin[j1] : 0.0f);
    }

    const size_t blk0 = (size_t)blockIdx.x * CTAB;
    copy4(xs, h0 + blk0 * RV, tid);
    __syncthreads();

    float h[RV];
#pragma unroll
    for (int j = 0; j < RV; ++j) h[j] = xs[tid * RV + j];

#pragma unroll 1
    for (int t = 0; t < RT; ++t) {
        __syncthreads();
        copy4(xs, g_scratch + t * PLANE + blk0 * RV, tid);
        __syncthreads();

        u64 acc[NJP];
#pragma unroll
        for (int jp = 0; jp < NJP; ++jp) acc[jp] = bias2[jp];

#pragma unroll
        for (int k = 0; k < RV; ++k) {
            const u64 xk2 = pkdup(xs[tid * RV + k]);
            const u64 hk2 = pkdup(h[k]);
            const ulonglong2* wr = w2 + k * NJP;
#pragma unroll
            for (int jp = 0; jp < NJP; ++jp) {
                ulonglong2 w = wr[jp];
                acc[jp] = ffma2(w.x, xk2, acc[jp]);
                acc[jp] = ffma2(w.y, hk2, acc[jp]);
            }
        }
#pragma unroll
        for (int jp = 0; jp < NJP; ++jp) {
            float a0, a1;
            upk2(acc[jp], a0, a1);
            h[2 * jp] = tanh_fast(a0);
            if (2 * jp + 1 < RV) h[2 * jp + 1] = tanh_fast(a1);
        }
    }

    // linear + tanh
    u64 lacc[NJP];
#pragma unroll
    for (int jp = 0; jp < NJP; ++jp) lacc[jp] = bl[jp];
#pragma unroll
    for (int k = 0; k < RV; ++k) {
        const u64 hk2 = pkdup(h[k]);
        const u64* wr = wl + k * NJP;
#pragma unroll
        for (int jp = 0; jp < NJP; ++jp)
            lacc[jp] = ffma2(wr[jp], hk2, lacc[jp]);   // broadcast LDS.64
    }

    float y[2 * NJP];
#pragma unroll
    for (int jp = 0; jp < NJP; ++jp) {
        float a0, a1;
        upk2(lacc[jp], a0, a1);
        y[2 * jp] = tanh_fast(a0);
        y[2 * jp + 1] = (2 * jp + 1 < RV) ? tanh_fast(a1) : -1e30f;
    }

    // softmax over V
    float m = y[0];
#pragma unroll
    for (int j = 1; j < RV; ++j) m = fmaxf(m, y[j]);
    float s = 0.0f;
#pragma unroll
    for (int j = 0; j < RV; ++j) { y[j] = __expf(y[j] - m); s += y[j]; }
    const float inv = __fdividef(1.0f, s);

    // stage + coalesced flat store
    __syncthreads();
#pragma unroll
    for (int j = 0; j < RV; ++j) xs[tid * RV + j] = y[j] * inv;
    __syncthreads();
    copy4(out + blk0 * RV, xs, tid);
}

extern "C" void kernel_launch(void* const* d_in, const int* in_sizes, int n_in,
                              void* d_out, int out_size)
{
    const float* inp  = (const float*)d_in[0];  // [B,T,V]
    const float* h0   = (const float*)d_in[1];  // [L,B,V]
    const float* Wih  = (const float*)d_in[2];  // [L,V,V]
    const float* Whh  = (const float*)d_in[3];  // [L,V,V]
    const float* bih  = (const float*)d_in[4];  // [L,V]
    const float* bhh  = (const float*)d_in[5];  // [L,V]
    const float* Wlin = (const float*)d_in[6];  // [V,V]
    const float* blin = (const float*)d_in[7];  // [V]
    float* out = (float*)d_out;                 // [B,V]

    (void)in_sizes; (void)n_in; (void)out_size;

    const dim3 grid(RB / CTAB), block(CTAB);

    // layer 0: inp [B,T,V] -> scratch [T,B,V]
    rnn_layer<<<grid, block>>>(inp, 1, h0, Wih, Whh, bih, bhh);
    // layer 1: scratch -> scratch (in-place per (t, CTA-block))
    rnn_layer<<<grid, block>>>(nullptr, 0, h0 + (size_t)RB * RV,
                               Wih + RV * RV, Whh + RV * RV,
                               bih + RV, bhh + RV);
    // layer 2 + linear + tanh + softmax
    rnn_final<<<grid, block>>>(h0 + 2 * (size_t)RB * RV,
                               Wih + 2 * RV * RV, Whh + 2 * RV * RV,
                               bih + 2 * RV, bhh + 2 * RV,
                               Wlin, blin, out);
}

// round 11
// speedup vs baseline: 10.4497x; 1.4338x over previous
#include <cuda_runtime.h>

#define RB 131072
#define RT 6
#define RV 31
#define NJP 16           // j-pairs; j=31 zero-padded
#define XS  (RT * RV)    // 186, row stride of inp [B,T,V]
#define CTAB 128
#define PLANE ((size_t)RB * RV)
#define BLKF  (CTAB * RV)   // 3968 floats per (t, CTA) block
#define BLKF4 (BLKF / 4)    // 992

// Inter-layer activation scratch, TIME-MAJOR [T][B][V].
__device__ float g_scratch[(size_t)RT * RB * RV];

typedef unsigned long long u64;

__device__ __forceinline__ u64 pkdup(float a) {
    u64 r;
    asm("mov.b64 %0, {%1, %1};" : "=l"(r) : "f"(a));
    return r;
}
__device__ __forceinline__ u64 pk2(float a, float b) {
    u64 r;
    asm("mov.b64 %0, {%1, %2};" : "=l"(r) : "f"(a), "f"(b));
    return r;
}
__device__ __forceinline__ void upk2(u64 v, float& x, float& y) {
    asm("mov.b64 {%0, %1}, %2;" : "=f"(x), "=f"(y) : "l"(v));
}
__device__ __forceinline__ u64 ffma2(u64 a, u64 b, u64 c) {
    u64 d;
    asm("fma.rn.f32x2 %0, %1, %2, %3;" : "=l"(d) : "l"(a), "l"(b), "l"(c));
    return d;
}
__device__ __forceinline__ float tanh_fast(float x) {
    float e = __expf(2.0f * x);
    return 1.0f - __fdividef(2.0f, e + 1.0f);
}

// ---- cp.async helpers --------------------------------------------------
__device__ __forceinline__ unsigned su32(const void* p) {
    return (unsigned)__cvta_generic_to_shared(p);
}
__device__ __forceinline__ void cpa16(unsigned s, const void* g) {
    asm volatile("cp.async.ca.shared.global [%0], [%1], 16;" :: "r"(s), "l"(g));
}
__device__ __forceinline__ void cpa4(unsigned s, const void* g) {
    asm volatile("cp.async.ca.shared.global [%0], [%1], 4;" :: "r"(s), "l"(g));
}
#define CP_COMMIT() asm volatile("cp.async.commit_group;")
#define CP_WAIT0()  asm volatile("cp.async.wait_group 0;" ::: "memory")

// flat async prefetch of one 3968-float block (992 x 16B)
__device__ __forceinline__ void pf_flat(float* sdst, const float* gsrc, int tid) {
    unsigned sb = su32(sdst);
#pragma unroll
    for (int it = 0; it < 8; ++it) {
        int i = tid + CTAB * it;
        if (it < 7 || i < BLKF4)
            cpa16(sb + 16u * i, (const float4*)gsrc + i);
    }
}
// strided async prefetch from inp [B,T,V]: src = inp + blk0*186 + t*31
__device__ __forceinline__ void pf_strided(float* sdst, const float* gsrc, int tid) {
    unsigned sb = su32(sdst);
#pragma unroll
    for (int it = 0; it < RV; ++it) {
        int i = tid + CTAB * it;            // < 3968 always
        int r = i / RV, c = i - r * RV;
        cpa4(sb + 4u * i, gsrc + r * XS + c);
    }
}
// coalesced coop store of one block (smem -> gmem)
__device__ __forceinline__ void st_flat(float* gdst, const float* ssrc, int tid) {
#pragma unroll
    for (int it = 0; it < 8; ++it) {
        int i = tid + CTAB * it;
        if (it < 7 || i < BLKF4)
            ((float4*)gdst)[i] = ((const float4*)ssrc)[i];
    }
}

// w2[k*NJP+jp] = { {Wih[j0,k],Wih[j1,k]}, {Whh[j0,k],Whh[j1,k]} }, j1==31 -> 0
__device__ __forceinline__ void fill_w(ulonglong2* w2, u64* bias2,
                                       const float* __restrict__ Wih,
                                       const float* __restrict__ Whh,
                                       const float* __restrict__ bih,
                                       const float* __restrict__ bhh,
                                       int tid)
{
    for (int i = tid; i < RV * NJP; i += CTAB) {
        int k = i / NJP, jp = i - k * NJP;
        int j0 = 2 * jp, j1 = j0 + 1;
        float a0 = Wih[j0 * RV + k];
        float a1 = (j1 < RV) ? Wih[j1 * RV + k] : 0.0f;
        float c0 = Whh[j0 * RV + k];
        float c1 = (j1 < RV) ? Whh[j1 * RV + k] : 0.0f;
        w2[i].x = pk2(a0, a1);
        w2[i].y = pk2(c0, c1);
    }
    if (tid < NJP) {
        int j0 = 2 * tid, j1 = j0 + 1;
        bias2[tid] = pk2(bih[j0] + bhh[j0],
                         (j1 < RV) ? (bih[j1] + bhh[j1]) : 0.0f);
    }
}

// core step: acc = bias + Wih*x + Whh*h, from own smem x row + h regs
__device__ __forceinline__ void rnn_step(u64* acc, const float* xrow,
                                         const float* h,
                                         const ulonglong2* w2, const u64* bias2)
{
#pragma unroll
    for (int jp = 0; jp < NJP; ++jp) acc[jp] = bias2[jp];
#pragma unroll
    for (int k = 0; k < RV; ++k) {
        const u64 xk2 = pkdup(xrow[k]);
        const u64 hk2 = pkdup(h[k]);
        const ulonglong2* wr = w2 + k * NJP;
#pragma unroll
        for (int jp = 0; jp < NJP; ++jp) {
            ulonglong2 w = wr[jp];              // broadcast LDS.128
            acc[jp] = ffma2(w.x, xk2, acc[jp]);
            acc[jp] = ffma2(w.y, hk2, acc[jp]);
        }
    }
}

// One RNN layer over all T steps; one batch element per thread.
__global__ void __launch_bounds__(CTAB, 4)
rnn_layer(const float* xin_ext, int use_ext_in,
          const float* __restrict__ h0,
          const float* __restrict__ Wih, const float* __restrict__ Whh,
          const float* __restrict__ bih, const float* __restrict__ bhh)
{
    __shared__ ulonglong2 w2[RV * NJP];     // 7936 B
    __shared__ u64 bias2[NJP];
    __shared__ float xb0[BLKF];             // double-buffered staging
    __shared__ float xb1[BLKF];

    const int tid = threadIdx.x;
    fill_w(w2, bias2, Wih, Whh, bih, bhh, tid);

    const size_t blk0 = (size_t)blockIdx.x * CTAB;

    // h0 (contiguous block) -> xb0 -> regs
    pf_flat(xb0, h0 + blk0 * RV, tid);
    CP_COMMIT(); CP_WAIT0();
    __syncthreads();

    float h[RV];
#pragma unroll
    for (int j = 0; j < RV; ++j) h[j] = xb0[tid * RV + j];

    // x[0] -> xb1 (xb0 reads above must complete first -> wait+sync below)
    if (use_ext_in) pf_strided(xb1, xin_ext + blk0 * XS, tid);
    else            pf_flat(xb1, g_scratch + blk0 * RV, tid);
    CP_COMMIT(); CP_WAIT0();
    __syncthreads();

#pragma unroll 1
    for (int t = 0; t < RT; ++t) {
        float* cur = ((t & 1) == 0) ? xb1 : xb0;
        float* nxt = ((t & 1) == 0) ? xb0 : xb1;

        // prefetch x[t+1] into nxt (async; no reg cost, no stall)
        if (t + 1 < RT) {
            if (use_ext_in)
                pf_strided(nxt, xin_ext + blk0 * XS + (t + 1) * RV, tid);
            else
                pf_flat(nxt, g_scratch + (t + 1) * PLANE + blk0 * RV, tid);
        }
        CP_COMMIT();

        u64 acc[NJP];
        rnn_step(acc, cur + tid * RV, h, w2, bias2);

        // results -> own row of cur (re-used as output staging)
#pragma unroll
        for (int jp = 0; jp < NJP; ++jp) {
            float a0, a1;
            upk2(acc[jp], a0, a1);
            int j0 = 2 * jp, j1 = j0 + 1;
            float v0 = tanh_fast(a0);
            h[j0] = v0;
            cur[tid * RV + j0] = v0;
            if (j1 < RV) {
                float v1 = tanh_fast(a1);
                h[j1] = v1;
                cur[tid * RV + j1] = v1;
            }
        }
        CP_WAIT0();
        __syncthreads();             // nxt ready; all cur writes done
        st_flat(g_scratch + t * PLANE + blk0 * RV, cur, tid);
        __syncthreads();             // cur store-reads done (prefetch target at t+1)
    }
}

// Layer 2 recurrence (no activation stores) + linear + tanh + softmax.
__global__ void __launch_bounds__(CTAB, 4)
rnn_final(const float* __restrict__ h0,
          const float* __restrict__ Wih, const float* __restrict__ Whh,
          const float* __restrict__ bih, const float* __restrict__ bhh,
          const float* __restrict__ Wlin, const float* __restrict__ blin,
          float* __restrict__ out)
{
    __shared__ ulonglong2 w2[RV * NJP];
    __shared__ u64 bias2[NJP];
    __shared__ u64 wl[RV * NJP];
    __shared__ u64 bl[NJP];
    __shared__ float xb0[BLKF];
    __shared__ float xb1[BLKF];

    const int tid = threadIdx.x;
    fill_w(w2, bias2, Wih, Whh, bih, bhh, tid);
    for (int i = tid; i < RV * NJP; i += CTAB) {
        int k = i / NJP, jp = i - k * NJP;
        int j0 = 2 * jp, j1 = j0 + 1;
        wl[i] = pk2(Wlin[j0 * RV + k], (j1 < RV) ? Wlin[j1 * RV + k] : 0.0f);
    }
    if (tid < NJP) {
        int j0 = 2 * tid, j1 = j0 + 1;
        bl[tid] = pk2(blin[j0], (j1 < RV) ? blin[j1] : 0.0f);
    }

    const size_t blk0 = (size_t)blockIdx.x * CTAB;

    pf_flat(xb0, h0 + blk0 * RV, tid);
    CP_COMMIT(); CP_WAIT0();
    __syncthreads();

    float h[RV];
#pragma unroll
    for (int j = 0; j < RV; ++j) h[j] = xb0[tid * RV + j];

    pf_flat(xb1, g_scratch + blk0 * RV, tid);
    CP_COMMIT(); CP_WAIT0();
    __syncthreads();

#pragma unroll 1
    for (int t = 0; t < RT; ++t) {
        float* cur = ((t & 1) == 0) ? xb1 : xb0;
        float* nxt = ((t & 1) == 0) ? xb0 : xb1;

        if (t + 1 < RT)
            pf_flat(nxt, g_scratch + (t + 1) * PLANE + blk0 * RV, tid);
        CP_COMMIT();

        u64 acc[NJP];
        rnn_step(acc, cur + tid * RV, h, w2, bias2);

#pragma unroll
        for (int jp = 0; jp < NJP; ++jp) {
            float a0, a1;
            upk2(acc[jp], a0, a1);
            h[2 * jp] = tanh_fast(a0);
            if (2 * jp + 1 < RV) h[2 * jp + 1] = tanh_fast(a1);
        }
        CP_WAIT0();
        __syncthreads();             // nxt ready; cur own-row reads done
    }

    // linear + tanh
    u64 lacc[NJP];
#pragma unroll
    for (int jp = 0; jp < NJP; ++jp) lacc[jp] = bl[jp];
#pragma unroll
    for (int k = 0; k < RV; ++k) {
        const u64 hk2 = pkdup(h[k]);
        const u64* wr = wl + k * NJP;
#pragma unroll
        for (int jp = 0; jp < NJP; ++jp)
            lacc[jp] = ffma2(wr[jp], hk2, lacc[jp]);
    }

    float y[2 * NJP];
#pragma unroll
    for (int jp = 0; jp < NJP; ++jp) {
        float a0, a1;
        upk2(lacc[jp], a0, a1);
        y[2 * jp] = tanh_fast(a0);
        y[2 * jp + 1] = (2 * jp + 1 < RV) ? tanh_fast(a1) : -1e30f;
    }

    // softmax over V
    float m = y[0];
#pragma unroll
    for (int j = 1; j < RV; ++j) m = fmaxf(m, y[j]);
    float s = 0.0f;
#pragma unroll
    for (int j = 0; j < RV; ++j) { y[j] = __expf(y[j] - m); s += y[j]; }
    const float inv = __fdividef(1.0f, s);

    // stage + coalesced store (xb0 free after last sync)
#pragma unroll
    for (int j = 0; j < RV; ++j) xb0[tid * RV + j] = y[j] * inv;
    __syncthreads();
    st_flat(out + blk0 * RV, xb0, tid);
}

extern "C" void kernel_launch(void* const* d_in, const int* in_sizes, int n_in,
                              void* d_out, int out_size)
{
    const float* inp  = (const float*)d_in[0];  // [B,T,V]
    const float* h0   = (const float*)d_in[1];  // [L,B,V]
    const float* Wih  = (const float*)d_in[2];  // [L,V,V]
    const float* Whh  = (const float*)d_in[3];  // [L,V,V]
    const float* bih  = (const float*)d_in[4];  // [L,V]
    const float* bhh  = (const float*)d_in[5];  // [L,V]
    const float* Wlin = (const float*)d_in[6];  // [V,V]
    const float* blin = (const float*)d_in[7];  // [V]
    float* out = (float*)d_out;                 // [B,V]

    (void)in_sizes; (void)n_in; (void)out_size;

    const dim3 grid(RB / CTAB), block(CTAB);

    rnn_layer<<<grid, block>>>(inp, 1, h0, Wih, Whh, bih, bhh);
    rnn_layer<<<grid, block>>>(nullptr, 0, h0 + (size_t)RB * RV,
                               Wih + RV * RV, Whh + RV * RV,
                               bih + RV, bhh + RV);
    rnn_final<<<grid, block>>>(h0 + 2 * (size_t)RB * RV,
                               Wih + 2 * RV * RV, Whh + 2 * RV * RV,
                               bih + 2 * RV, bhh + 2 * RV,
                               Wlin, blin, out);
}

// round 12
// speedup vs baseline: 11.1430x; 1.0664x over previous
#include <cuda_runtime.h>

#define RB 131072
#define RT 6
#define RV 31
#define NJP 16            // j-pairs; j=31 zero-padded
#define XS  (RT * RV)     // 186, row stride of inp [B,T,V]
#define CTAB 64           // threads per CTA
#define EPT 2             // batch elements per thread
#define BLKE (CTAB * EPT) // 128 batch elems per CTA
#define BLKF (BLKE * RV)  // 3968 floats per (t, CTA) block
#define BLKF4 (BLKF / 4)  // 992
#define PLANE ((size_t)RB * RV)

// Inter-layer activation scratch, TIME-MAJOR [T][B][V].
__device__ float g_scratch[(size_t)RT * RB * RV];

typedef unsigned long long u64;

__device__ __forceinline__ u64 pkdup(float a) {
    u64 r;
    asm("mov.b64 %0, {%1, %1};" : "=l"(r) : "f"(a));
    return r;
}
__device__ __forceinline__ u64 pk2(float a, float b) {
    u64 r;
    asm("mov.b64 %0, {%1, %2};" : "=l"(r) : "f"(a), "f"(b));
    return r;
}
__device__ __forceinline__ void upk2(u64 v, float& x, float& y) {
    asm("mov.b64 {%0, %1}, %2;" : "=f"(x), "=f"(y) : "l"(v));
}
__device__ __forceinline__ u64 ffma2(u64 a, u64 b, u64 c) {
    u64 d;
    asm("fma.rn.f32x2 %0, %1, %2, %3;" : "=l"(d) : "l"(a), "l"(b), "l"(c));
    return d;
}
__device__ __forceinline__ float tanh_fast(float x) {
    float e = __expf(2.0f * x);
    return 1.0f - __fdividef(2.0f, e + 1.0f);
}

// ---- cp.async helpers --------------------------------------------------
__device__ __forceinline__ unsigned su32(const void* p) {
    return (unsigned)__cvta_generic_to_shared(p);
}
__device__ __forceinline__ void cpa16(unsigned s, const void* g) {
    asm volatile("cp.async.ca.shared.global [%0], [%1], 16;" :: "r"(s), "l"(g));
}
__device__ __forceinline__ void cpa4(unsigned s, const void* g) {
    asm volatile("cp.async.ca.shared.global [%0], [%1], 4;" :: "r"(s), "l"(g));
}
#define CP_COMMIT() asm volatile("cp.async.commit_group;")
#define CP_WAIT0()  asm volatile("cp.async.wait_group 0;" ::: "memory")

// flat async prefetch of one 3968-float block (992 x 16B), 64 threads
__device__ __forceinline__ void pf_flat(float* sdst, const float* gsrc, int tid) {
    unsigned sb = su32(sdst);
#pragma unroll
    for (int it = 0; it < BLKF4 / CTAB + 1; ++it) {
        int i = tid + CTAB * it;
        if (i < BLKF4) cpa16(sb + 16u * i, (const float4*)gsrc + i);
    }
}
// strided async prefetch from inp [B,T,V]
__device__ __forceinline__ void pf_strided(float* sdst, const float* gsrc, int tid) {
    unsigned sb = su32(sdst);
#pragma unroll
    for (int it = 0; it < BLKF / CTAB; ++it) {   // 62 iters
        int i = tid + CTAB * it;
        int r = i / RV, c = i - r * RV;
        cpa4(sb + 4u * i, gsrc + r * XS + c);
    }
}
// coalesced coop store of one block (smem -> gmem)
__device__ __forceinline__ void st_flat(float* gdst, const float* ssrc, int tid) {
#pragma unroll
    for (int it = 0; it < BLKF4 / CTAB + 1; ++it) {
        int i = tid + CTAB * it;
        if (i < BLKF4) ((float4*)gdst)[i] = ((const float4*)ssrc)[i];
    }
}

// w2[k*NJP+jp] = { {Wih[j0,k],Wih[j1,k]}, {Whh[j0,k],Whh[j1,k]} }, j1==31 -> 0
__device__ __forceinline__ void fill_w(ulonglong2* w2, u64* bias2,
                                       const float* __restrict__ Wih,
                                       const float* __restrict__ Whh,
                                       const float* __restrict__ bih,
                                       const float* __restrict__ bhh,
                                       int tid)
{
    for (int i = tid; i < RV * NJP; i += CTAB) {
        int k = i / NJP, jp = i - k * NJP;
        int j0 = 2 * jp, j1 = j0 + 1;
        float a0 = Wih[j0 * RV + k];
        float a1 = (j1 < RV) ? Wih[j1 * RV + k] : 0.0f;
        float c0 = Whh[j0 * RV + k];
        float c1 = (j1 < RV) ? Whh[j1 * RV + k] : 0.0f;
        w2[i].x = pk2(a0, a1);
        w2[i].y = pk2(c0, c1);
    }
    if (tid < NJP) {
        int j0 = 2 * tid, j1 = j0 + 1;
        bias2[tid] = pk2(bih[j0] + bhh[j0],
                         (j1 < RV) ? (bih[j1] + bhh[j1]) : 0.0f);
    }
}

// dual-element step: each weight LDS.128 feeds 4 FFMA2
__device__ __forceinline__ void rnn_step2(u64* acc0, u64* acc1,
                                          const float* xr0, const float* xr1,
                                          const float* ha, const float* hb,
                                          const ulonglong2* w2, const u64* bias2)
{
#pragma unroll
    for (int jp = 0; jp < NJP; ++jp) { acc0[jp] = bias2[jp]; acc1[jp] = bias2[jp]; }
#pragma unroll
    for (int k = 0; k < RV; ++k) {
        const u64 x0 = pkdup(xr0[k]);
        const u64 h0 = pkdup(ha[k]);
        const u64 x1 = pkdup(xr1[k]);
        const u64 h1 = pkdup(hb[k]);
        const ulonglong2* wr = w2 + k * NJP;
#pragma unroll
        for (int jp = 0; jp < NJP; ++jp) {
            ulonglong2 w = wr[jp];               // one broadcast LDS.128
            acc0[jp] = ffma2(w.x, x0, acc0[jp]);
            acc0[jp] = ffma2(w.y, h0, acc0[jp]);
            acc1[jp] = ffma2(w.x, x1, acc1[jp]);
            acc1[jp] = ffma2(w.y, h1, acc1[jp]);
        }
    }
}

// One RNN layer over all T steps; two batch elements per thread.
__global__ void __launch_bounds__(CTAB, 4)
rnn_layer(const float* xin_ext, int use_ext_in,
          const float* __restrict__ h0g,
          const float* __restrict__ Wih, const float* __restrict__ Whh,
          const float* __restrict__ bih, const float* __restrict__ bhh)
{
    __shared__ ulonglong2 w2[RV * NJP];     // 7936 B
    __shared__ u64 bias2[NJP];
    __shared__ float xb0[BLKF];             // double-buffered staging
    __shared__ float xb1[BLKF];

    const int tid = threadIdx.x;
    fill_w(w2, bias2, Wih, Whh, bih, bhh, tid);

    const size_t blk0 = (size_t)blockIdx.x * BLKE;
    const int r0 = 2 * tid, r1 = 2 * tid + 1;   // this thread's rows in block

    pf_flat(xb0, h0g + blk0 * RV, tid);
    CP_COMMIT(); CP_WAIT0();
    __syncthreads();

    float ha[RV], hb[RV];
#pragma unroll
    for (int j = 0; j < RV; ++j) { ha[j] = xb0[r0 * RV + j]; hb[j] = xb0[r1 * RV + j]; }

    if (use_ext_in) pf_strided(xb1, xin_ext + blk0 * XS, tid);
    else            pf_flat(xb1, g_scratch + blk0 * RV, tid);
    CP_COMMIT(); CP_WAIT0();
    __syncthreads();

#pragma unroll 1
    for (int t = 0; t < RT; ++t) {
        float* cur = ((t & 1) == 0) ? xb1 : xb0;
        float* nxt = ((t & 1) == 0) ? xb0 : xb1;

        if (t + 1 < RT) {
            if (use_ext_in)
                pf_strided(nxt, xin_ext + blk0 * XS + (t + 1) * RV, tid);
            else
                pf_flat(nxt, g_scratch + (t + 1) * PLANE + blk0 * RV, tid);
        }
        CP_COMMIT();

        u64 acc0[NJP], acc1[NJP];
        rnn_step2(acc0, acc1, cur + r0 * RV, cur + r1 * RV, ha, hb, w2, bias2);

#pragma unroll
        for (int jp = 0; jp < NJP; ++jp) {
            float a0, a1, b0, b1;
            upk2(acc0[jp], a0, a1);
            upk2(acc1[jp], b0, b1);
            int j0 = 2 * jp, j1 = j0 + 1;
            float v = tanh_fast(a0);
            ha[j0] = v; cur[r0 * RV + j0] = v;
            v = tanh_fast(b0);
            hb[j0] = v; cur[r1 * RV + j0] = v;
            if (j1 < RV) {
                v = tanh_fast(a1);
                ha[j1] = v; cur[r0 * RV + j1] = v;
                v = tanh_fast(b1);
                hb[j1] = v; cur[r1 * RV + j1] = v;
            }
        }
        CP_WAIT0();
        __syncthreads();             // nxt ready; all cur writes done
        st_flat(g_scratch + t * PLANE + blk0 * RV, cur, tid);
        __syncthreads();             // cur reads done before it becomes prefetch dst
    }
}

// Layer 2 recurrence (no activation stores) + linear + tanh + softmax.
__global__ void __launch_bounds__(CTAB, 4)
rnn_final(const float* __restrict__ h0g,
          const float* __restrict__ Wih, const float* __restrict__ Whh,
          const float* __restrict__ bih, const float* __restrict__ bhh,
          const float* __restrict__ Wlin, const float* __restrict__ blin,
          float* __restrict__ out)
{
    __shared__ ulonglong2 w2[RV * NJP];
    __shared__ u64 bias2[NJP];
    __shared__ u64 wl[RV * NJP];
    __shared__ u64 bl[NJP];
    __shared__ float xb0[BLKF];
    __shared__ float xb1[BLKF];

    const int tid = threadIdx.x;
    fill_w(w2, bias2, Wih, Whh, bih, bhh, tid);
    for (int i = tid; i < RV * NJP; i += CTAB) {
        int k = i / NJP, jp = i - k * NJP;
        int j0 = 2 * jp, j1 = j0 + 1;
        wl[i] = pk2(Wlin[j0 * RV + k], (j1 < RV) ? Wlin[j1 * RV + k] : 0.0f);
    }
    if (tid < NJP) {
        int j0 = 2 * tid, j1 = j0 + 1;
        bl[tid] = pk2(blin[j0], (j1 < RV) ? blin[j1] : 0.0f);
    }

    const size_t blk0 = (size_t)blockIdx.x * BLKE;
    const int r0 = 2 * tid, r1 = 2 * tid + 1;

    pf_flat(xb0, h0g + blk0 * RV, tid);
    CP_COMMIT(); CP_WAIT0();
    __syncthreads();

    float ha[RV], hb[RV];
#pragma unroll
    for (int j = 0; j < RV; ++j) { ha[j] = xb0[r0 * RV + j]; hb[j] = xb0[r1 * RV + j]; }

    pf_flat(xb1, g_scratch + blk0 * RV, tid);
    CP_COMMIT(); CP_WAIT0();
    __syncthreads();

#pragma unroll 1
    for (int t = 0; t < RT; ++t) {
        float* cur = ((t & 1) == 0) ? xb1 : xb0;
        float* nxt = ((t & 1) == 0) ? xb0 : xb1;

        if (t + 1 < RT)
            pf_flat(nxt, g_scratch + (t + 1) * PLANE + blk0 * RV, tid);
        CP_COMMIT();

        u64 acc0[NJP], acc1[NJP];
        rnn_step2(acc0, acc1, cur + r0 * RV, cur + r1 * RV, ha, hb, w2, bias2);

#pragma unroll
        for (int jp = 0; jp < NJP; ++jp) {
            float a0, a1, b0, b1;
            upk2(acc0[jp], a0, a1);
            upk2(acc1[jp], b0, b1);
            ha[2 * jp] = tanh_fast(a0);
            hb[2 * jp] = tanh_fast(b0);
            if (2 * jp + 1 < RV) {
                ha[2 * jp + 1] = tanh_fast(a1);
                hb[2 * jp + 1] = tanh_fast(b1);
            }
        }
        CP_WAIT0();
        __syncthreads();
    }

    // linear + tanh (both elements; weight LDS.64 feeds 2 FFMA2)
    u64 l0[NJP], l1[NJP];
#pragma unroll
    for (int jp = 0; jp < NJP; ++jp) { l0[jp] = bl[jp]; l1[jp] = bl[jp]; }
#pragma unroll
    for (int k = 0; k < RV; ++k) {
        const u64 h0d = pkdup(ha[k]);
        const u64 h1d = pkdup(hb[k]);
        const u64* wr = wl + k * NJP;
#pragma unroll
        for (int jp = 0; jp < NJP; ++jp) {
            u64 w = wr[jp];
            l0[jp] = ffma2(w, h0d, l0[jp]);
            l1[jp] = ffma2(w, h1d, l1[jp]);
        }
    }

    float ya[2 * NJP], yb[2 * NJP];
#pragma unroll
    for (int jp = 0; jp < NJP; ++jp) {
        float a0, a1, b0, b1;
        upk2(l0[jp], a0, a1);
        upk2(l1[jp], b0, b1);
        ya[2 * jp] = tanh_fast(a0);
        yb[2 * jp] = tanh_fast(b0);
        ya[2 * jp + 1] = (2 * jp + 1 < RV) ? tanh_fast(a1) : -1e30f;
        yb[2 * jp + 1] = (2 * jp + 1 < RV) ? tanh_fast(b1) : -1e30f;
    }

    // softmax per element, stage into xb0, coalesced store
    {
        float m = ya[0];
#pragma unroll
        for (int j = 1; j < RV; ++j) m = fmaxf(m, ya[j]);
        float s = 0.0f;
#pragma unroll
        for (int j = 0; j < RV; ++j) { ya[j] = __expf(ya[j] - m); s += ya[j]; }
        float inv = __fdividef(1.0f, s);
#pragma unroll
        for (int j = 0; j < RV; ++j) xb0[r0 * RV + j] = ya[j] * inv;
    }
    {
        float m = yb[0];
#pragma unroll
        for (int j = 1; j < RV; ++j) m = fmaxf(m, yb[j]);
        float s = 0.0f;
#pragma unroll
        for (int j = 0; j < RV; ++j) { yb[j] = __expf(yb[j] - m); s += yb[j]; }
        float inv = __fdividef(1.0f, s);
#pragma unroll
        for (int j = 0; j < RV; ++j) xb0[r1 * RV + j] = yb[j] * inv;
    }
    __syncthreads();
    st_flat(out + blk0 * RV, xb0, tid);
}

extern "C" void kernel_launch(void* const* d_in, const int* in_sizes, int n_in,
                              void* d_out, int out_size)
{
    const float* inp  = (const float*)d_in[0];  // [B,T,V]
    const float* h0   = (const float*)d_in[1];  // [L,B,V]
    const float* Wih  = (const float*)d_in[2];  // [L,V,V]
    const float* Whh  = (const float*)d_in[3];  // [L,V,V]
    const float* bih  = (const float*)d_in[4];  // [L,V]
    const float* bhh  = (const float*)d_in[5];  // [L,V]
    const float* Wlin = (const float*)d_in[6];  // [V,V]
    const float* blin = (const float*)d_in[7];  // [V]
    float* out = (float*)d_out;                 // [B,V]

    (void)in_sizes; (void)n_in; (void)out_size;

    const dim3 grid(RB / BLKE), block(CTAB);    // 1024 x 64

    rnn_layer<<<grid, block>>>(inp, 1, h0, Wih, Whh, bih, bhh);
    rnn_layer<<<grid, block>>>(nullptr, 0, h0 + (size_t)RB * RV,
                               Wih + RV * RV, Whh + RV * RV,
                               bih + RV, bhh + RV);
    rnn_final<<<grid, block>>>(h0 + 2 * (size_t)RB * RV,
                               Wih + 2 * RV * RV, Whh + 2 * RV * RV,
                               bih + 2 * RV, bhh + 2 * RV,
                               Wlin, blin, out);
}